// round 15
// baseline (speedup 1.0000x reference)
#include <cuda_runtime.h>
#include <cuda_bf16.h>
#include <math.h>
#include <stdint.h>

#define BATCH  8
#define FDIM   512
#define KDIM   64
#define EDIM   128
#define NHEAD  4
#define LWIN   64
#define FFI    128
#define NWIN   4
#define QK_SCALE 0.17677669529663687f
#define LN_EPS 1e-5f

// fragment-packed weights: one uint4 = {b0(kt even), b1(kt even), b0(kt odd), b1(kt odd)}
__device__ uint4 g_wqkvp[6144];   // 384x128
__device__ uint4 g_wprojp[2048];  // 128x128
__device__ uint4 g_wfc1p[8192];   // 512x128, chunk-contiguous
__device__ uint4 g_wfc2p[8192];   // 128x512, chunk-contiguous

__device__ __forceinline__ uint32_t sa(const void* p) {
    return (uint32_t)__cvta_generic_to_shared(p);
}
__device__ __forceinline__ void ldmx4(uint32_t (&r)[4], uint32_t a) {
    asm volatile("ldmatrix.sync.aligned.m8n8.x4.shared.b16 {%0,%1,%2,%3}, [%4];"
                 : "=r"(r[0]), "=r"(r[1]), "=r"(r[2]), "=r"(r[3]) : "r"(a));
}
__device__ __forceinline__ void ldmx2(uint32_t (&r)[2], uint32_t a) {
    asm volatile("ldmatrix.sync.aligned.m8n8.x2.shared.b16 {%0,%1}, [%2];"
                 : "=r"(r[0]), "=r"(r[1]) : "r"(a));
}
__device__ __forceinline__ void ldmx2t(uint32_t (&r)[2], uint32_t a) {
    asm volatile("ldmatrix.sync.aligned.m8n8.x2.trans.shared.b16 {%0,%1}, [%2];"
                 : "=r"(r[0]), "=r"(r[1]) : "r"(a));
}
__device__ __forceinline__ void mma16816(float (&d)[4], const uint32_t (&A)[4],
                                         uint32_t b0, uint32_t b1) {
    asm volatile("mma.sync.aligned.m16n8k16.row.col.f32.bf16.bf16.f32 "
                 "{%0,%1,%2,%3},{%4,%5,%6,%7},{%8,%9},{%0,%1,%2,%3};"
                 : "+f"(d[0]), "+f"(d[1]), "+f"(d[2]), "+f"(d[3])
                 : "r"(A[0]), "r"(A[1]), "r"(A[2]), "r"(A[3]), "r"(b0), "r"(b1));
}
__device__ __forceinline__ uint32_t packbf(float lo, float hi) {
    __nv_bfloat162 t = __floats2bfloat162_rn(lo, hi);
    return *reinterpret_cast<uint32_t*>(&t);
}

// ---- weight packers (destinations named INSIDE device code) ----
__global__ void pack_qkvp(const float* __restrict__ w) {
    int tid = blockIdx.x * 256 + threadIdx.x;    // 96 blocks -> 24576
    int e = tid & 3, lane = (tid >> 2) & 31, u = (tid >> 7) & 3, jg = tid >> 9;
    int r = lane >> 2, c2 = (lane & 3) * 2;
    int row = jg * 8 + r;
    int cb = 32 * u + (e >> 1) * 16 + (e & 1) * 8 + c2;
    __nv_bfloat16* dst = (__nv_bfloat16*)g_wqkvp;
    dst[tid * 2]     = __float2bfloat16_rn(w[row * 128 + cb]);
    dst[tid * 2 + 1] = __float2bfloat16_rn(w[row * 128 + cb + 1]);
}
__global__ void pack_projp(const float* __restrict__ w) {
    int tid = blockIdx.x * 256 + threadIdx.x;    // 32 blocks -> 8192
    int e = tid & 3, lane = (tid >> 2) & 31, u = (tid >> 7) & 3, jg = tid >> 9;
    int r = lane >> 2, c2 = (lane & 3) * 2;
    int row = jg * 8 + r;
    int cb = 32 * u + (e >> 1) * 16 + (e & 1) * 8 + c2;
    __nv_bfloat16* dst = (__nv_bfloat16*)g_wprojp;
    dst[tid * 2]     = __float2bfloat16_rn(w[row * 128 + cb]);
    dst[tid * 2 + 1] = __float2bfloat16_rn(w[row * 128 + cb + 1]);
}
__global__ void conv_fc1p(const float* __restrict__ w) {
    int tid = blockIdx.x * 256 + threadIdx.x;    // 128 blocks -> 32768
    int e = tid & 3, lane = (tid >> 2) & 31, u = (tid >> 7) & 3, jg = tid >> 9;
    int r = lane >> 2, c2 = (lane & 3) * 2;
    int row = jg * 8 + r;
    int cb = 32 * u + (e >> 1) * 16 + (e & 1) * 8 + c2;
    __nv_bfloat16* dst = (__nv_bfloat16*)g_wfc1p;
    dst[tid * 2]     = __float2bfloat16_rn(w[row * 128 + cb]);
    dst[tid * 2 + 1] = __float2bfloat16_rn(w[row * 128 + cb + 1]);
}
__global__ void conv_fc2p(const float* __restrict__ w) {
    int tid = blockIdx.x * 256 + threadIdx.x;    // 128 blocks -> 32768
    int e = tid & 3, lane = (tid >> 2) & 31, u = (tid >> 7) & 15, jg = tid >> 11;
    int r = lane >> 2, c2 = (lane & 3) * 2;
    int row = jg * 8 + r;
    int cb = 32 * u + (e >> 1) * 16 + (e & 1) * 8 + c2;
    int rec = (u * 16 + jg) * 32 + lane;
    __nv_bfloat16* dst = (__nv_bfloat16*)g_wfc2p;
    dst[(rec * 4 + e) * 2]     = __float2bfloat16_rn(w[row * 512 + cb]);
    dst[(rec * 4 + e) * 2 + 1] = __float2bfloat16_rn(w[row * 512 + cb + 1]);
}

// ============================================================================
// Kernel 1: TWO windows per block (M=128). 512 threads = 16 warps.
// GEMM phases: warp = m32 x n32. Attention: warp = (win, head, m32-half).
// smem: XN,QS,KS,VS,AO bf16 [128][136]; OUTS f32 [128][132] aliases XN+QS.
// ============================================================================
#define S1 136
#define SM1_BYTES (5 * 128 * 136 * 2)

__global__ __launch_bounds__(512)
void attn_kernel(const float* __restrict__ x,
                 const float* __restrict__ qkv_b,
                 const float* __restrict__ proj_b,
                 const float* __restrict__ ln1_s,
                 const float* __restrict__ ln1_b,
                 float* __restrict__ out)
{
    extern __shared__ char smem[];
    __nv_bfloat16* XN = (__nv_bfloat16*)smem;
    __nv_bfloat16* QS = XN + 128 * S1;
    __nv_bfloat16* KS = QS + 128 * S1;
    __nv_bfloat16* VS = KS + 128 * S1;
    __nv_bfloat16* AO = VS + 128 * S1;
    float* OUTS = (float*)smem;   // [128][132] f32; spans XN+QS (dead by Phase D writes)

    const int tid  = threadIdx.x;
    const int lane = tid & 31;
    const int warp = tid >> 5;            // 0..15
    const int n  = blockIdx.x;            // 2048 blocks, 2 windows each
    const int wp = n & 1;
    const int fi = (n >> 1) & (FFI - 1);
    const int b  = n >> 8;

    const int r  = lane >> 2;
    const int c2 = (lane & 3) * 2;
    const int arow  = lane & 15;
    const int acol8 = (lane >> 4) * 8;

    // GEMM-phase warp tiling: m32 (mh 0-3) x n32 (nh 0-3)
    const int mh = warp & 3;
    const int nh = warp >> 2;

    // Phase A: gather (roll -2 along frames) + LN1 -> XN (bf16), 4 thr/token
    {
        const int row = tid >> 2;          // 0..127
        const int q   = tid & 3;
        const int win = row >> 6;
        const int l   = row & 63;
        const int tp = l >> 4, w16 = l & 15;
        int srcf = fi * 4 + tp + 2;
        if (srcf >= FDIM) srcf -= FDIM;
        const int kk = (2 * wp + win) * 16 + w16;
        const float* xp = x + (((size_t)b * FDIM + srcf) * KDIM + kk) * EDIM + q * 32;
        float v[32];
#pragma unroll
        for (int i = 0; i < 8; i++) {
            float4 t = reinterpret_cast<const float4*>(xp)[i];
            v[4*i] = t.x; v[4*i+1] = t.y; v[4*i+2] = t.z; v[4*i+3] = t.w;
        }
        float s1 = 0.f, s2 = 0.f;
#pragma unroll
        for (int i = 0; i < 32; i++) { s1 += v[i]; s2 += v[i] * v[i]; }
        s1 += __shfl_xor_sync(0xffffffffu, s1, 1);
        s2 += __shfl_xor_sync(0xffffffffu, s2, 1);
        s1 += __shfl_xor_sync(0xffffffffu, s1, 2);
        s2 += __shfl_xor_sync(0xffffffffu, s2, 2);
        const float mean = s1 * (1.f / 128.f);
        const float rstd = rsqrtf(s2 * (1.f / 128.f) - mean * mean + LN_EPS);
#pragma unroll
        for (int ii = 0; ii < 4; ii++) {
            uint32_t w4[4];
#pragma unroll
            for (int k = 0; k < 4; k++) {
                const int i = ii * 4 + k;
                const int c = q * 32 + 2 * i;
                float a0 = (v[2*i]   - mean) * rstd * ln1_s[c]     + ln1_b[c];
                float a1 = (v[2*i+1] - mean) * rstd * ln1_s[c + 1] + ln1_b[c + 1];
                w4[k] = packbf(a0, a1);
            }
            *(uint4*)&XN[row * S1 + q * 32 + 8 * ii] =
                make_uint4(w4[0], w4[1], w4[2], w4[3]);
        }
    }
    __syncthreads();

    // Phase B: QKV GEMM (128x384x128). warp: m32 x n32, packed B LDG.128.
    {
#pragma unroll
        for (int p = 0; p < 3; p++) {
            float acc[2][4][4];
#pragma unroll
            for (int mt = 0; mt < 2; mt++)
#pragma unroll
                for (int j = 0; j < 4; j++)
#pragma unroll
                    for (int e = 0; e < 4; e++) acc[mt][j][e] = 0.f;
#pragma unroll
            for (int u = 0; u < 4; u++) {
                uint32_t Ae[2][4], Ao[2][4];
#pragma unroll
                for (int mt = 0; mt < 2; mt++) {
                    const int row = (mh * 2 + mt) * 16 + arow;
                    ldmx4(Ae[mt], sa(&XN[row * S1 + (2*u) * 16 + acol8]));
                    ldmx4(Ao[mt], sa(&XN[row * S1 + (2*u+1) * 16 + acol8]));
                }
#pragma unroll
                for (int j = 0; j < 4; j++) {
                    const uint4 B = g_wqkvp[(((p * 16 + nh * 4 + j) * 4 + u) * 32) + lane];
#pragma unroll
                    for (int mt = 0; mt < 2; mt++) {
                        mma16816(acc[mt][j], Ae[mt], B.x, B.y);
                        mma16816(acc[mt][j], Ao[mt], B.z, B.w);
                    }
                }
            }
            __nv_bfloat16* dst = (p == 0) ? QS : (p == 1) ? KS : VS;
#pragma unroll
            for (int mt = 0; mt < 2; mt++)
#pragma unroll
                for (int j = 0; j < 4; j++) {
                    const int col = nh * 32 + j * 8 + c2;
                    const float b0v = qkv_b[p * 128 + col];
                    const float b1v = qkv_b[p * 128 + col + 1];
                    float v00 = acc[mt][j][0] + b0v, v01 = acc[mt][j][1] + b1v;
                    float v10 = acc[mt][j][2] + b0v, v11 = acc[mt][j][3] + b1v;
                    if (p == 0) { v00 *= QK_SCALE; v01 *= QK_SCALE; v10 *= QK_SCALE; v11 *= QK_SCALE; }
                    const int row = (mh * 2 + mt) * 16 + r;
                    *(uint32_t*)&dst[row * S1 + col]       = packbf(v00, v01);
                    *(uint32_t*)&dst[(row + 8) * S1 + col] = packbf(v10, v11);
                }
        }
    }
    __syncthreads();

    // Phase C: scores + mask + softmax + PV. warp = (win, head, m-half).
    {
        const int win = warp >> 3;
        const int h   = (warp >> 1) & 3;
        const int m0w = (warp & 1) * 32;
        const bool maskwin = (fi == FFI - 1);
        const int base = win * 64;

        uint32_t qa[2][2][4];
#pragma unroll
        for (int mt = 0; mt < 2; mt++)
#pragma unroll
            for (int kt = 0; kt < 2; kt++)
                ldmx4(qa[mt][kt], sa(&QS[(base + m0w + mt * 16 + arow) * S1 + h * 32 + kt * 16 + acol8]));

        float s[2][8][4];
#pragma unroll
        for (int mt = 0; mt < 2; mt++)
#pragma unroll
            for (int j = 0; j < 8; j++)
#pragma unroll
                for (int e = 0; e < 4; e++) s[mt][j][e] = 0.f;

#pragma unroll
        for (int j = 0; j < 8; j++)
#pragma unroll
            for (int kt = 0; kt < 2; kt++) {
                uint32_t kb[2];
                ldmx2(kb, sa(&KS[(base + j * 8 + (lane & 7)) * S1 + h * 32 + kt * 16 + ((lane >> 3) & 1) * 8]));
                mma16816(s[0][j], qa[0][kt], kb[0], kb[1]);
                mma16816(s[1][j], qa[1][kt], kb[0], kb[1]);
            }

#pragma unroll
        for (int mt = 0; mt < 2; mt++) {
            const int ra = m0w + mt * 16 + r;
            const int rb = ra + 8;
            const bool qah = (ra < 32), qbh = (rb < 32);
            float mxa = -1e30f, mxb = -1e30f;
#pragma unroll
            for (int j = 0; j < 8; j++) {
                const bool cq = (j < 4);
                float* v = s[mt][j];
                if (maskwin && (qah != cq)) { v[0] = -10000.f; v[1] = -10000.f; }
                else { if (v[0] == 0.f) v[0] = -10000.f; if (v[1] == 0.f) v[1] = -10000.f; }
                if (maskwin && (qbh != cq)) { v[2] = -10000.f; v[3] = -10000.f; }
                else { if (v[2] == 0.f) v[2] = -10000.f; if (v[3] == 0.f) v[3] = -10000.f; }
                mxa = fmaxf(mxa, fmaxf(v[0], v[1]));
                mxb = fmaxf(mxb, fmaxf(v[2], v[3]));
            }
            mxa = fmaxf(mxa, __shfl_xor_sync(0xffffffffu, mxa, 1));
            mxa = fmaxf(mxa, __shfl_xor_sync(0xffffffffu, mxa, 2));
            mxb = fmaxf(mxb, __shfl_xor_sync(0xffffffffu, mxb, 1));
            mxb = fmaxf(mxb, __shfl_xor_sync(0xffffffffu, mxb, 2));
            float sma = 0.f, smb = 0.f;
#pragma unroll
            for (int j = 0; j < 8; j++) {
                float* v = s[mt][j];
                v[0] = __expf(v[0] - mxa); v[1] = __expf(v[1] - mxa);
                v[2] = __expf(v[2] - mxb); v[3] = __expf(v[3] - mxb);
                sma += v[0] + v[1]; smb += v[2] + v[3];
            }
            sma += __shfl_xor_sync(0xffffffffu, sma, 1);
            sma += __shfl_xor_sync(0xffffffffu, sma, 2);
            smb += __shfl_xor_sync(0xffffffffu, smb, 1);
            smb += __shfl_xor_sync(0xffffffffu, smb, 2);
            const float ia = 1.f / sma, ib = 1.f / smb;
#pragma unroll
            for (int j = 0; j < 8; j++) {
                float* v = s[mt][j];
                v[0] *= ia; v[1] *= ia; v[2] *= ib; v[3] *= ib;
            }
        }

        float o[2][4][4];
#pragma unroll
        for (int mt = 0; mt < 2; mt++)
#pragma unroll
            for (int j2 = 0; j2 < 4; j2++)
#pragma unroll
                for (int e = 0; e < 4; e++) o[mt][j2][e] = 0.f;
#pragma unroll
        for (int kt = 0; kt < 4; kt++) {
            uint32_t pa[2][4];
#pragma unroll
            for (int mt = 0; mt < 2; mt++) {
                pa[mt][0] = packbf(s[mt][2*kt][0],   s[mt][2*kt][1]);
                pa[mt][1] = packbf(s[mt][2*kt][2],   s[mt][2*kt][3]);
                pa[mt][2] = packbf(s[mt][2*kt+1][0], s[mt][2*kt+1][1]);
                pa[mt][3] = packbf(s[mt][2*kt+1][2], s[mt][2*kt+1][3]);
            }
#pragma unroll
            for (int j2 = 0; j2 < 4; j2++) {
                uint32_t vb[2];
                ldmx2t(vb, sa(&VS[(base + kt * 16 + arow) * S1 + h * 32 + j2 * 8]));
                mma16816(o[0][j2], pa[0], vb[0], vb[1]);
                mma16816(o[1][j2], pa[1], vb[0], vb[1]);
            }
        }
#pragma unroll
        for (int mt = 0; mt < 2; mt++)
#pragma unroll
            for (int j2 = 0; j2 < 4; j2++) {
                const int row = base + m0w + mt * 16 + r;
                const int col = h * 32 + j2 * 8 + c2;
                *(uint32_t*)&AO[row * S1 + col]       = packbf(o[mt][j2][0], o[mt][j2][1]);
                *(uint32_t*)&AO[(row + 8) * S1 + col] = packbf(o[mt][j2][2], o[mt][j2][3]);
            }
    }
    __syncthreads();

    // Phase D: proj (128x128x128). warp: m32 x n32, packed B LDG.128. -> OUTS
    {
        float acc[2][4][4];
#pragma unroll
        for (int mt = 0; mt < 2; mt++)
#pragma unroll
            for (int j = 0; j < 4; j++)
#pragma unroll
                for (int e = 0; e < 4; e++) acc[mt][j][e] = 0.f;
#pragma unroll
        for (int u = 0; u < 4; u++) {
            uint32_t Ae[2][4], Ao[2][4];
#pragma unroll
            for (int mt = 0; mt < 2; mt++) {
                const int row = (mh * 2 + mt) * 16 + arow;
                ldmx4(Ae[mt], sa(&AO[row * S1 + (2*u) * 16 + acol8]));
                ldmx4(Ao[mt], sa(&AO[row * S1 + (2*u+1) * 16 + acol8]));
            }
#pragma unroll
            for (int j = 0; j < 4; j++) {
                const uint4 B = g_wprojp[(((nh * 4 + j) * 4 + u) * 32) + lane];
#pragma unroll
                for (int mt = 0; mt < 2; mt++) {
                    mma16816(acc[mt][j], Ae[mt], B.x, B.y);
                    mma16816(acc[mt][j], Ao[mt], B.z, B.w);
                }
            }
        }
        __syncthreads();   // all QS-region reads done before OUTS overwrite
#pragma unroll
        for (int mt = 0; mt < 2; mt++)
#pragma unroll
            for (int j = 0; j < 4; j++) {
                const int col = nh * 32 + j * 8 + c2;
                const float b0v = proj_b[col], b1v = proj_b[col + 1];
                const int row = (mh * 2 + mt) * 16 + r;
                *(float2*)&OUTS[row * 132 + col] =
                    make_float2(acc[mt][j][0] + b0v, acc[mt][j][1] + b1v);
                *(float2*)&OUTS[(row + 8) * 132 + col] =
                    make_float2(acc[mt][j][2] + b0v, acc[mt][j][3] + b1v);
            }
    }
    __syncthreads();

    // Phase E: roll(+2 along window tokens) + window reverse + residual
    {
        const int lp  = tid >> 2;          // destination token 0..127
        const int q   = tid & 3;
        const int win = lp >> 6;
        const int l   = lp & 63;
        const int tp = l >> 4, w16 = l & 15;
        const int lsrc = win * 64 + ((l - 2 + LWIN) & (LWIN - 1));
        const int frame = fi * 4 + tp;
        const int kk = (2 * wp + win) * 16 + w16;
        const size_t base = (((size_t)b * FDIM + frame) * KDIM + kk) * EDIM + q * 32;
        const float* xp = x + base;
        float* op = out + base;
#pragma unroll
        for (int i = 0; i < 8; i++) {
            float4 t = reinterpret_cast<const float4*>(xp)[i];
            const int c = q * 32 + 4 * i;
            t.x += OUTS[lsrc * 132 + c];
            t.y += OUTS[lsrc * 132 + c + 1];
            t.z += OUTS[lsrc * 132 + c + 2];
            t.w += OUTS[lsrc * 132 + c + 3];
            reinterpret_cast<float4*>(op)[i] = t;
        }
    }
}

// ============================================================================
// Kernel 2: LN2 + fc1 + GELU + fc2 + residual. (round-12 exact, passing)
// ============================================================================
#define S2 136
#define XS_BYTES (128 * 136 * 2)
#define WCHUNK_U4 2048
#define SM2_BYTES (XS_BYTES + WCHUNK_U4 * 16)

__global__ __launch_bounds__(256)
void mlp_kernel(float* __restrict__ io,
                const float* __restrict__ ln2_s,
                const float* __restrict__ ln2_b,
                const float* __restrict__ fc1_b,
                const float* __restrict__ fc2_b)
{
    extern __shared__ char smem[];
    __nv_bfloat16* XS = (__nv_bfloat16*)smem;
    uint4* WB1 = (uint4*)(smem + XS_BYTES);
    uint4* WB2 = WB1 + 1024;

    const int tid  = threadIdx.x;
    const int lane = tid & 31;
    const int warp = tid >> 5;
    const size_t tok0 = (size_t)blockIdx.x * 128;

    const int r  = lane >> 2;
    const int c2 = (lane & 3) * 2;
    const int arow  = lane & 15;
    const int acol8 = (lane >> 4) * 8;

    {
        const int l = warp * 16 + (lane >> 1);
        const int q = lane & 1;
        const float* xp = io + (tok0 + l) * EDIM + q * 64;
        float v[64];
#pragma unroll
        for (int i = 0; i < 16; i++) {
            float4 t = reinterpret_cast<const float4*>(xp)[i];
            v[4*i] = t.x; v[4*i+1] = t.y; v[4*i+2] = t.z; v[4*i+3] = t.w;
        }
        float s1 = 0.f, s2 = 0.f;
#pragma unroll
        for (int i = 0; i < 64; i++) { s1 += v[i]; s2 += v[i] * v[i]; }
        s1 += __shfl_xor_sync(0xffffffffu, s1, 1);
        s2 += __shfl_xor_sync(0xffffffffu, s2, 1);
        const float mean = s1 * (1.f / 128.f);
        const float rstd = rsqrtf(s2 * (1.f / 128.f) - mean * mean + LN_EPS);
#pragma unroll
        for (int i = 0; i < 32; i++) {
            const int c = q * 64 + 2 * i;
            float a0 = (v[2*i]   - mean) * rstd * ln2_s[c]     + ln2_b[c];
            float a1 = (v[2*i+1] - mean) * rstd * ln2_s[c + 1] + ln2_b[c + 1];
            *(uint32_t*)&XS[l * S2 + c] = packbf(a0, a1);
        }
    }
    __syncwarp();

    uint32_t a[8][4];
#pragma unroll
    for (int kt = 0; kt < 8; kt++)
        ldmx4(a[kt], sa(&XS[(warp * 16 + arow) * S2 + kt * 16 + acol8]));

    float hacc[16][4];
#pragma unroll
    for (int j2 = 0; j2 < 16; j2++)
#pragma unroll
        for (int e = 0; e < 4; e++) hacc[j2][e] = 0.f;

    for (int nc = 0; nc < 8; nc++) {
        __syncthreads();
#pragma unroll
        for (int i = 0; i < 4; i++) {
            const int idx = i * 256 + tid;
            WB1[idx] = g_wfc1p[nc * 1024 + idx];
            WB2[idx] = g_wfc2p[nc * 1024 + idx];
        }
        __syncthreads();

        float c1[8][4];
#pragma unroll
        for (int j = 0; j < 8; j++)
#pragma unroll
            for (int e = 0; e < 4; e++) c1[j][e] = 0.f;
#pragma unroll
        for (int u = 0; u < 4; u++)
#pragma unroll
            for (int j = 0; j < 8; j++) {
                const uint4 B = WB1[(j * 4 + u) * 32 + lane];
                mma16816(c1[j], a[2*u],     B.x, B.y);
                mma16816(c1[j], a[2*u + 1], B.z, B.w);
            }

        uint32_t pa[4][4];
#pragma unroll
        for (int t = 0; t < 4; t++) {
#pragma unroll
            for (int p = 0; p < 2; p++) {
                const int j = 2 * t + p;
                const int gn = nc * 64 + j * 8 + c2;
                const float b0v = fc1_b[gn], b1v = fc1_b[gn + 1];
                float v0 = c1[j][0] + b0v, v1 = c1[j][1] + b1v;
                float v2 = c1[j][2] + b0v, v3 = c1[j][3] + b1v;
                v0 = 0.5f * v0 * (1.f + erff(v0 * 0.70710678118654752f));
                v1 = 0.5f * v1 * (1.f + erff(v1 * 0.70710678118654752f));
                v2 = 0.5f * v2 * (1.f + erff(v2 * 0.70710678118654752f));
                v3 = 0.5f * v3 * (1.f + erff(v3 * 0.70710678118654752f));
                pa[t][2*p]     = packbf(v0, v1);
                pa[t][2*p + 1] = packbf(v2, v3);
            }
        }

#pragma unroll
        for (int u2 = 0; u2 < 2; u2++)
#pragma unroll
            for (int j2 = 0; j2 < 16; j2++) {
                const uint4 B = WB2[(u2 * 16 + j2) * 32 + lane];
                mma16816(hacc[j2], pa[2*u2],     B.x, B.y);
                mma16816(hacc[j2], pa[2*u2 + 1], B.z, B.w);
            }
    }

    {
        float* base0 = io + (tok0 + warp * 16 + r) * EDIM;
        float* base1 = base0 + 8 * EDIM;
#pragma unroll
        for (int j2 = 0; j2 < 16; j2++) {
            const int col = j2 * 8 + c2;
            const float b0v = fc2_b[col], b1v = fc2_b[col + 1];
            float2 t0 = *(float2*)(base0 + col);
            t0.x += hacc[j2][0] + b0v;
            t0.y += hacc[j2][1] + b1v;
            *(float2*)(base0 + col) = t0;
            float2 t1 = *(float2*)(base1 + col);
            t1.x += hacc[j2][2] + b0v;
            t1.y += hacc[j2][3] + b1v;
            *(float2*)(base1 + col) = t1;
        }
    }
}

extern "C" void kernel_launch(void* const* d_in, const int* in_sizes, int n_in,
                              void* d_out, int out_size)
{
    const float* x      = (const float*)d_in[0];
    const float* qkv_w  = (const float*)d_in[1];
    const float* qkv_b  = (const float*)d_in[2];
    const float* proj_w = (const float*)d_in[3];
    const float* proj_b = (const float*)d_in[4];
    const float* ln1_s  = (const float*)d_in[5];
    const float* ln1_b  = (const float*)d_in[6];
    const float* ln2_s  = (const float*)d_in[7];
    const float* ln2_b  = (const float*)d_in[8];
    const float* fc1_w  = (const float*)d_in[9];
    const float* fc1_b  = (const float*)d_in[10];
    const float* fc2_w  = (const float*)d_in[11];
    const float* fc2_b  = (const float*)d_in[12];
    float* out = (float*)d_out;

    cudaFuncSetAttribute(attn_kernel, cudaFuncAttributeMaxDynamicSharedMemorySize, SM1_BYTES);
    cudaFuncSetAttribute(mlp_kernel,  cudaFuncAttributeMaxDynamicSharedMemorySize, SM2_BYTES);

    pack_qkvp<<<96, 256>>>(qkv_w);
    pack_projp<<<32, 256>>>(proj_w);
    conv_fc1p<<<128, 256>>>(fc1_w);
    conv_fc2p<<<128, 256>>>(fc2_w);
    attn_kernel<<<2048, 512, SM1_BYTES>>>(x, qkv_b, proj_b, ln1_s, ln1_b, out);
    mlp_kernel<<<2048, 256, SM2_BYTES>>>(out, ln2_s, ln2_b, fc1_b, fc2_b);
}

// round 16
// speedup vs baseline: 1.1374x; 1.1374x over previous
#include <cuda_runtime.h>
#include <cuda_bf16.h>
#include <math.h>
#include <stdint.h>

#define BATCH  8
#define FDIM   512
#define KDIM   64
#define EDIM   128
#define NHEAD  4
#define LWIN   64
#define FFI    128
#define NWIN   4
#define QK_SCALE 0.17677669529663687f
#define LN_EPS 1e-5f

// fragment-packed weights: one uint4 = {b0(kt even), b1(kt even), b0(kt odd), b1(kt odd)}
__device__ uint4 g_wqkvp[6144];   // 384x128
__device__ uint4 g_wprojp[2048];  // 128x128
__device__ uint4 g_wfc1p[8192];   // 512x128, chunk-contiguous
__device__ uint4 g_wfc2p[8192];   // 128x512, chunk-contiguous

__device__ __forceinline__ uint32_t sa(const void* p) {
    return (uint32_t)__cvta_generic_to_shared(p);
}
__device__ __forceinline__ void ldmx4(uint32_t (&r)[4], uint32_t a) {
    asm volatile("ldmatrix.sync.aligned.m8n8.x4.shared.b16 {%0,%1,%2,%3}, [%4];"
                 : "=r"(r[0]), "=r"(r[1]), "=r"(r[2]), "=r"(r[3]) : "r"(a));
}
__device__ __forceinline__ void ldmx2(uint32_t (&r)[2], uint32_t a) {
    asm volatile("ldmatrix.sync.aligned.m8n8.x2.shared.b16 {%0,%1}, [%2];"
                 : "=r"(r[0]), "=r"(r[1]) : "r"(a));
}
__device__ __forceinline__ void ldmx2t(uint32_t (&r)[2], uint32_t a) {
    asm volatile("ldmatrix.sync.aligned.m8n8.x2.trans.shared.b16 {%0,%1}, [%2];"
                 : "=r"(r[0]), "=r"(r[1]) : "r"(a));
}
__device__ __forceinline__ void mma16816(float (&d)[4], const uint32_t (&A)[4],
                                         uint32_t b0, uint32_t b1) {
    asm volatile("mma.sync.aligned.m16n8k16.row.col.f32.bf16.bf16.f32 "
                 "{%0,%1,%2,%3},{%4,%5,%6,%7},{%8,%9},{%0,%1,%2,%3};"
                 : "+f"(d[0]), "+f"(d[1]), "+f"(d[2]), "+f"(d[3])
                 : "r"(A[0]), "r"(A[1]), "r"(A[2]), "r"(A[3]), "r"(b0), "r"(b1));
}
__device__ __forceinline__ uint32_t packbf(float lo, float hi) {
    __nv_bfloat162 t = __floats2bfloat162_rn(lo, hi);
    return *reinterpret_cast<uint32_t*>(&t);
}
// fast GELU: tanh form with single-instruction MUFU tanh (activations are
// rounded to bf16 right after, so exact erf precision is not needed)
__device__ __forceinline__ float gelu_fast(float v) {
    float t = 0.7978845608028654f * fmaf(0.044715f * v, v * v, v);
    float y;
    asm("tanh.approx.f32 %0, %1;" : "=f"(y) : "f"(t));
    return 0.5f * v * (1.f + y);
}

// ---- weight packers (destinations named INSIDE device code) ----
__global__ void pack_qkvp(const float* __restrict__ w) {
    int tid = blockIdx.x * 256 + threadIdx.x;    // 96 blocks -> 24576
    int e = tid & 3, lane = (tid >> 2) & 31, u = (tid >> 7) & 3, jg = tid >> 9;
    int r = lane >> 2, c2 = (lane & 3) * 2;
    int row = jg * 8 + r;
    int cb = 32 * u + (e >> 1) * 16 + (e & 1) * 8 + c2;
    __nv_bfloat16* dst = (__nv_bfloat16*)g_wqkvp;
    dst[tid * 2]     = __float2bfloat16_rn(w[row * 128 + cb]);
    dst[tid * 2 + 1] = __float2bfloat16_rn(w[row * 128 + cb + 1]);
}
__global__ void pack_projp(const float* __restrict__ w) {
    int tid = blockIdx.x * 256 + threadIdx.x;    // 32 blocks -> 8192
    int e = tid & 3, lane = (tid >> 2) & 31, u = (tid >> 7) & 3, jg = tid >> 9;
    int r = lane >> 2, c2 = (lane & 3) * 2;
    int row = jg * 8 + r;
    int cb = 32 * u + (e >> 1) * 16 + (e & 1) * 8 + c2;
    __nv_bfloat16* dst = (__nv_bfloat16*)g_wprojp;
    dst[tid * 2]     = __float2bfloat16_rn(w[row * 128 + cb]);
    dst[tid * 2 + 1] = __float2bfloat16_rn(w[row * 128 + cb + 1]);
}
__global__ void conv_fc1p(const float* __restrict__ w) {
    int tid = blockIdx.x * 256 + threadIdx.x;    // 128 blocks -> 32768
    int e = tid & 3, lane = (tid >> 2) & 31, u = (tid >> 7) & 3, jg = tid >> 9;
    int r = lane >> 2, c2 = (lane & 3) * 2;
    int row = jg * 8 + r;
    int cb = 32 * u + (e >> 1) * 16 + (e & 1) * 8 + c2;
    __nv_bfloat16* dst = (__nv_bfloat16*)g_wfc1p;
    dst[tid * 2]     = __float2bfloat16_rn(w[row * 128 + cb]);
    dst[tid * 2 + 1] = __float2bfloat16_rn(w[row * 128 + cb + 1]);
}
__global__ void conv_fc2p(const float* __restrict__ w) {
    int tid = blockIdx.x * 256 + threadIdx.x;    // 128 blocks -> 32768
    int e = tid & 3, lane = (tid >> 2) & 31, u = (tid >> 7) & 15, jg = tid >> 11;
    int r = lane >> 2, c2 = (lane & 3) * 2;
    int row = jg * 8 + r;
    int cb = 32 * u + (e >> 1) * 16 + (e & 1) * 8 + c2;
    int rec = (u * 16 + jg) * 32 + lane;
    __nv_bfloat16* dst = (__nv_bfloat16*)g_wfc2p;
    dst[(rec * 4 + e) * 2]     = __float2bfloat16_rn(w[row * 512 + cb]);
    dst[(rec * 4 + e) * 2 + 1] = __float2bfloat16_rn(w[row * 512 + cb + 1]);
}

// ============================================================================
// Kernel 1: TWO windows per block (M=128). 256 threads = 8 warps.
// GEMM phases: warp = m32 x n64, packed-uint4 B from global. (round-12 exact)
// ============================================================================
#define S1 136
#define SM1_BYTES (5 * 128 * 136 * 2)

__global__ __launch_bounds__(256)
void attn_kernel(const float* __restrict__ x,
                 const float* __restrict__ qkv_b,
                 const float* __restrict__ proj_b,
                 const float* __restrict__ ln1_s,
                 const float* __restrict__ ln1_b,
                 float* __restrict__ out)
{
    extern __shared__ char smem[];
    __nv_bfloat16* XN = (__nv_bfloat16*)smem;
    __nv_bfloat16* QS = XN + 128 * S1;
    __nv_bfloat16* KS = QS + 128 * S1;
    __nv_bfloat16* VS = KS + 128 * S1;
    __nv_bfloat16* AO = VS + 128 * S1;
    float* OUTS = (float*)smem;   // [128][132] f32; spans XN+QS (dead by Phase D writes)

    const int tid  = threadIdx.x;
    const int lane = tid & 31;
    const int warp = tid >> 5;
    const int n  = blockIdx.x;            // 2048 blocks, 2 windows each
    const int wp = n & 1;
    const int fi = (n >> 1) & (FFI - 1);
    const int b  = n >> 8;

    const int r  = lane >> 2;
    const int c2 = (lane & 3) * 2;
    const int arow  = lane & 15;
    const int acol8 = (lane >> 4) * 8;

    // GEMM-phase warp tiling: m32 (mh) x n64 (nh)
    const int mh = warp & 3;
    const int nh = warp >> 2;

    // Phase A: gather (roll -2 along frames) + LN1 -> XN (bf16), 2 thr/token
    {
        const int row = tid >> 1;          // 0..127
        const int q   = tid & 1;
        const int win = row >> 6;
        const int l   = row & 63;
        const int tp = l >> 4, w16 = l & 15;
        int srcf = fi * 4 + tp + 2;
        if (srcf >= FDIM) srcf -= FDIM;
        const int kk = (2 * wp + win) * 16 + w16;
        const float* xp = x + (((size_t)b * FDIM + srcf) * KDIM + kk) * EDIM + q * 64;
        float v[64];
#pragma unroll
        for (int i = 0; i < 16; i++) {
            float4 t = reinterpret_cast<const float4*>(xp)[i];
            v[4*i] = t.x; v[4*i+1] = t.y; v[4*i+2] = t.z; v[4*i+3] = t.w;
        }
        float s1 = 0.f, s2 = 0.f;
#pragma unroll
        for (int i = 0; i < 64; i++) { s1 += v[i]; s2 += v[i] * v[i]; }
        s1 += __shfl_xor_sync(0xffffffffu, s1, 1);
        s2 += __shfl_xor_sync(0xffffffffu, s2, 1);
        const float mean = s1 * (1.f / 128.f);
        const float rstd = rsqrtf(s2 * (1.f / 128.f) - mean * mean + LN_EPS);
#pragma unroll
        for (int ii = 0; ii < 8; ii++) {
            uint32_t w4[4];
#pragma unroll
            for (int k = 0; k < 4; k++) {
                const int i = ii * 4 + k;
                const int c = q * 64 + 2 * i;
                float a0 = (v[2*i]   - mean) * rstd * ln1_s[c]     + ln1_b[c];
                float a1 = (v[2*i+1] - mean) * rstd * ln1_s[c + 1] + ln1_b[c + 1];
                w4[k] = packbf(a0, a1);
            }
            *(uint4*)&XN[row * S1 + q * 64 + 8 * ii] =
                make_uint4(w4[0], w4[1], w4[2], w4[3]);
        }
    }
    __syncthreads();

    // Phase B: QKV GEMM (128x384x128). warp: m32 x n64, packed B LDG.128.
    {
#pragma unroll
        for (int p = 0; p < 3; p++) {
            float acc[2][8][4];
#pragma unroll
            for (int mt = 0; mt < 2; mt++)
#pragma unroll
                for (int j = 0; j < 8; j++)
#pragma unroll
                    for (int e = 0; e < 4; e++) acc[mt][j][e] = 0.f;
#pragma unroll
            for (int u = 0; u < 4; u++) {
                uint32_t Ae[2][4], Ao[2][4];
#pragma unroll
                for (int mt = 0; mt < 2; mt++) {
                    const int row = (mh * 2 + mt) * 16 + arow;
                    ldmx4(Ae[mt], sa(&XN[row * S1 + (2*u) * 16 + acol8]));
                    ldmx4(Ao[mt], sa(&XN[row * S1 + (2*u+1) * 16 + acol8]));
                }
#pragma unroll
                for (int j = 0; j < 8; j++) {
                    const uint4 B = g_wqkvp[(((p * 16 + nh * 8 + j) * 4 + u) * 32) + lane];
#pragma unroll
                    for (int mt = 0; mt < 2; mt++) {
                        mma16816(acc[mt][j], Ae[mt], B.x, B.y);
                        mma16816(acc[mt][j], Ao[mt], B.z, B.w);
                    }
                }
            }
            __nv_bfloat16* dst = (p == 0) ? QS : (p == 1) ? KS : VS;
#pragma unroll
            for (int mt = 0; mt < 2; mt++)
#pragma unroll
                for (int j = 0; j < 8; j++) {
                    const int col = nh * 64 + j * 8 + c2;
                    const float b0v = qkv_b[p * 128 + col];
                    const float b1v = qkv_b[p * 128 + col + 1];
                    float v00 = acc[mt][j][0] + b0v, v01 = acc[mt][j][1] + b1v;
                    float v10 = acc[mt][j][2] + b0v, v11 = acc[mt][j][3] + b1v;
                    if (p == 0) { v00 *= QK_SCALE; v01 *= QK_SCALE; v10 *= QK_SCALE; v11 *= QK_SCALE; }
                    const int row = (mh * 2 + mt) * 16 + r;
                    *(uint32_t*)&dst[row * S1 + col]       = packbf(v00, v01);
                    *(uint32_t*)&dst[(row + 8) * S1 + col] = packbf(v10, v11);
                }
        }
    }
    __syncthreads();

    // Phase C: scores + mask + softmax + PV (looped over the 2 windows)
    {
        const int h   = warp >> 1;
        const int m0w = (warp & 1) * 32;
        const bool maskwin = (fi == FFI - 1);

#pragma unroll
        for (int win = 0; win < 2; win++) {
            const int base = win * 64;

            uint32_t qa[2][2][4];
#pragma unroll
            for (int mt = 0; mt < 2; mt++)
#pragma unroll
                for (int kt = 0; kt < 2; kt++)
                    ldmx4(qa[mt][kt], sa(&QS[(base + m0w + mt * 16 + arow) * S1 + h * 32 + kt * 16 + acol8]));

            float s[2][8][4];
#pragma unroll
            for (int mt = 0; mt < 2; mt++)
#pragma unroll
                for (int j = 0; j < 8; j++)
#pragma unroll
                    for (int e = 0; e < 4; e++) s[mt][j][e] = 0.f;

#pragma unroll
            for (int j = 0; j < 8; j++)
#pragma unroll
                for (int kt = 0; kt < 2; kt++) {
                    uint32_t kb[2];
                    ldmx2(kb, sa(&KS[(base + j * 8 + (lane & 7)) * S1 + h * 32 + kt * 16 + ((lane >> 3) & 1) * 8]));
                    mma16816(s[0][j], qa[0][kt], kb[0], kb[1]);
                    mma16816(s[1][j], qa[1][kt], kb[0], kb[1]);
                }

#pragma unroll
            for (int mt = 0; mt < 2; mt++) {
                const int ra = m0w + mt * 16 + r;
                const int rb = ra + 8;
                const bool qah = (ra < 32), qbh = (rb < 32);
                float mxa = -1e30f, mxb = -1e30f;
#pragma unroll
                for (int j = 0; j < 8; j++) {
                    const bool cq = (j < 4);
                    float* v = s[mt][j];
                    if (maskwin && (qah != cq)) { v[0] = -10000.f; v[1] = -10000.f; }
                    else { if (v[0] == 0.f) v[0] = -10000.f; if (v[1] == 0.f) v[1] = -10000.f; }
                    if (maskwin && (qbh != cq)) { v[2] = -10000.f; v[3] = -10000.f; }
                    else { if (v[2] == 0.f) v[2] = -10000.f; if (v[3] == 0.f) v[3] = -10000.f; }
                    mxa = fmaxf(mxa, fmaxf(v[0], v[1]));
                    mxb = fmaxf(mxb, fmaxf(v[2], v[3]));
                }
                mxa = fmaxf(mxa, __shfl_xor_sync(0xffffffffu, mxa, 1));
                mxa = fmaxf(mxa, __shfl_xor_sync(0xffffffffu, mxa, 2));
                mxb = fmaxf(mxb, __shfl_xor_sync(0xffffffffu, mxb, 1));
                mxb = fmaxf(mxb, __shfl_xor_sync(0xffffffffu, mxb, 2));
                float sma = 0.f, smb = 0.f;
#pragma unroll
                for (int j = 0; j < 8; j++) {
                    float* v = s[mt][j];
                    v[0] = __expf(v[0] - mxa); v[1] = __expf(v[1] - mxa);
                    v[2] = __expf(v[2] - mxb); v[3] = __expf(v[3] - mxb);
                    sma += v[0] + v[1]; smb += v[2] + v[3];
                }
                sma += __shfl_xor_sync(0xffffffffu, sma, 1);
                sma += __shfl_xor_sync(0xffffffffu, sma, 2);
                smb += __shfl_xor_sync(0xffffffffu, smb, 1);
                smb += __shfl_xor_sync(0xffffffffu, smb, 2);
                const float ia = 1.f / sma, ib = 1.f / smb;
#pragma unroll
                for (int j = 0; j < 8; j++) {
                    float* v = s[mt][j];
                    v[0] *= ia; v[1] *= ia; v[2] *= ib; v[3] *= ib;
                }
            }

            float o[2][4][4];
#pragma unroll
            for (int mt = 0; mt < 2; mt++)
#pragma unroll
                for (int j2 = 0; j2 < 4; j2++)
#pragma unroll
                    for (int e = 0; e < 4; e++) o[mt][j2][e] = 0.f;
#pragma unroll
            for (int kt = 0; kt < 4; kt++) {
                uint32_t pa[2][4];
#pragma unroll
                for (int mt = 0; mt < 2; mt++) {
                    pa[mt][0] = packbf(s[mt][2*kt][0],   s[mt][2*kt][1]);
                    pa[mt][1] = packbf(s[mt][2*kt][2],   s[mt][2*kt][3]);
                    pa[mt][2] = packbf(s[mt][2*kt+1][0], s[mt][2*kt+1][1]);
                    pa[mt][3] = packbf(s[mt][2*kt+1][2], s[mt][2*kt+1][3]);
                }
#pragma unroll
                for (int j2 = 0; j2 < 4; j2++) {
                    uint32_t vb[2];
                    ldmx2t(vb, sa(&VS[(base + kt * 16 + arow) * S1 + h * 32 + j2 * 8]));
                    mma16816(o[0][j2], pa[0], vb[0], vb[1]);
                    mma16816(o[1][j2], pa[1], vb[0], vb[1]);
                }
            }
#pragma unroll
            for (int mt = 0; mt < 2; mt++)
#pragma unroll
                for (int j2 = 0; j2 < 4; j2++) {
                    const int row = base + m0w + mt * 16 + r;
                    const int col = h * 32 + j2 * 8 + c2;
                    *(uint32_t*)&AO[row * S1 + col]       = packbf(o[mt][j2][0], o[mt][j2][1]);
                    *(uint32_t*)&AO[(row + 8) * S1 + col] = packbf(o[mt][j2][2], o[mt][j2][3]);
                }
        }
    }
    __syncthreads();

    // Phase D: proj (128x128x128). warp: m32 x n64, packed B LDG.128. -> OUTS
    {
        float acc[2][8][4];
#pragma unroll
        for (int mt = 0; mt < 2; mt++)
#pragma unroll
            for (int j = 0; j < 8; j++)
#pragma unroll
                for (int e = 0; e < 4; e++) acc[mt][j][e] = 0.f;
#pragma unroll
        for (int u = 0; u < 4; u++) {
            uint32_t Ae[2][4], Ao[2][4];
#pragma unroll
            for (int mt = 0; mt < 2; mt++) {
                const int row = (mh * 2 + mt) * 16 + arow;
                ldmx4(Ae[mt], sa(&AO[row * S1 + (2*u) * 16 + acol8]));
                ldmx4(Ao[mt], sa(&AO[row * S1 + (2*u+1) * 16 + acol8]));
            }
#pragma unroll
            for (int j = 0; j < 8; j++) {
                const uint4 B = g_wprojp[(((nh * 8 + j) * 4 + u) * 32) + lane];
#pragma unroll
                for (int mt = 0; mt < 2; mt++) {
                    mma16816(acc[mt][j], Ae[mt], B.x, B.y);
                    mma16816(acc[mt][j], Ao[mt], B.z, B.w);
                }
            }
        }
        __syncthreads();   // all QS-region reads done before OUTS overwrite
#pragma unroll
        for (int mt = 0; mt < 2; mt++)
#pragma unroll
            for (int j = 0; j < 8; j++) {
                const int col = nh * 64 + j * 8 + c2;
                const float b0v = proj_b[col], b1v = proj_b[col + 1];
                const int row = (mh * 2 + mt) * 16 + r;
                *(float2*)&OUTS[row * 132 + col] =
                    make_float2(acc[mt][j][0] + b0v, acc[mt][j][1] + b1v);
                *(float2*)&OUTS[(row + 8) * 132 + col] =
                    make_float2(acc[mt][j][2] + b0v, acc[mt][j][3] + b1v);
            }
    }
    __syncthreads();

    // Phase E: roll(+2 along window tokens) + window reverse + residual
    {
        const int lp  = tid >> 1;          // destination token 0..127
        const int q   = tid & 1;
        const int win = lp >> 6;
        const int l   = lp & 63;
        const int tp = l >> 4, w16 = l & 15;
        const int lsrc = win * 64 + ((l - 2 + LWIN) & (LWIN - 1));
        const int frame = fi * 4 + tp;
        const int kk = (2 * wp + win) * 16 + w16;
        const size_t base = (((size_t)b * FDIM + frame) * KDIM + kk) * EDIM + q * 64;
        const float* xp = x + base;
        float* op = out + base;
#pragma unroll
        for (int i = 0; i < 16; i++) {
            float4 t = reinterpret_cast<const float4*>(xp)[i];
            const int c = q * 64 + 4 * i;
            t.x += OUTS[lsrc * 132 + c];
            t.y += OUTS[lsrc * 132 + c + 1];
            t.z += OUTS[lsrc * 132 + c + 2];
            t.w += OUTS[lsrc * 132 + c + 3];
            reinterpret_cast<float4*>(op)[i] = t;
        }
    }
}

// ============================================================================
// Kernel 2: LN2 + fc1 + GELU(tanh.approx) + fc2 + residual.
// ============================================================================
#define S2 136
#define XS_BYTES (128 * 136 * 2)
#define WCHUNK_U4 2048
#define SM2_BYTES (XS_BYTES + WCHUNK_U4 * 16)

__global__ __launch_bounds__(256)
void mlp_kernel(float* __restrict__ io,
                const float* __restrict__ ln2_s,
                const float* __restrict__ ln2_b,
                const float* __restrict__ fc1_b,
                const float* __restrict__ fc2_b)
{
    extern __shared__ char smem[];
    __nv_bfloat16* XS = (__nv_bfloat16*)smem;
    uint4* WB1 = (uint4*)(smem + XS_BYTES);
    uint4* WB2 = WB1 + 1024;

    const int tid  = threadIdx.x;
    const int lane = tid & 31;
    const int warp = tid >> 5;
    const size_t tok0 = (size_t)blockIdx.x * 128;

    const int r  = lane >> 2;
    const int c2 = (lane & 3) * 2;
    const int arow  = lane & 15;
    const int acol8 = (lane >> 4) * 8;

    {
        const int l = warp * 16 + (lane >> 1);
        const int q = lane & 1;
        const float* xp = io + (tok0 + l) * EDIM + q * 64;
        float v[64];
#pragma unroll
        for (int i = 0; i < 16; i++) {
            float4 t = reinterpret_cast<const float4*>(xp)[i];
            v[4*i] = t.x; v[4*i+1] = t.y; v[4*i+2] = t.z; v[4*i+3] = t.w;
        }
        float s1 = 0.f, s2 = 0.f;
#pragma unroll
        for (int i = 0; i < 64; i++) { s1 += v[i]; s2 += v[i] * v[i]; }
        s1 += __shfl_xor_sync(0xffffffffu, s1, 1);
        s2 += __shfl_xor_sync(0xffffffffu, s2, 1);
        const float mean = s1 * (1.f / 128.f);
        const float rstd = rsqrtf(s2 * (1.f / 128.f) - mean * mean + LN_EPS);
#pragma unroll
        for (int i = 0; i < 32; i++) {
            const int c = q * 64 + 2 * i;
            float a0 = (v[2*i]   - mean) * rstd * ln2_s[c]     + ln2_b[c];
            float a1 = (v[2*i+1] - mean) * rstd * ln2_s[c + 1] + ln2_b[c + 1];
            *(uint32_t*)&XS[l * S2 + c] = packbf(a0, a1);
        }
    }
    __syncwarp();

    uint32_t a[8][4];
#pragma unroll
    for (int kt = 0; kt < 8; kt++)
        ldmx4(a[kt], sa(&XS[(warp * 16 + arow) * S2 + kt * 16 + acol8]));

    float hacc[16][4];
#pragma unroll
    for (int j2 = 0; j2 < 16; j2++)
#pragma unroll
        for (int e = 0; e < 4; e++) hacc[j2][e] = 0.f;

    for (int nc = 0; nc < 8; nc++) {
        __syncthreads();
#pragma unroll
        for (int i = 0; i < 4; i++) {
            const int idx = i * 256 + tid;
            WB1[idx] = g_wfc1p[nc * 1024 + idx];
            WB2[idx] = g_wfc2p[nc * 1024 + idx];
        }
        __syncthreads();

        float c1[8][4];
#pragma unroll
        for (int j = 0; j < 8; j++)
#pragma unroll
            for (int e = 0; e < 4; e++) c1[j][e] = 0.f;
#pragma unroll
        for (int u = 0; u < 4; u++)
#pragma unroll
            for (int j = 0; j < 8; j++) {
                const uint4 B = WB1[(j * 4 + u) * 32 + lane];
                mma16816(c1[j], a[2*u],     B.x, B.y);
                mma16816(c1[j], a[2*u + 1], B.z, B.w);
            }

        uint32_t pa[4][4];
#pragma unroll
        for (int t = 0; t < 4; t++) {
#pragma unroll
            for (int p = 0; p < 2; p++) {
                const int j = 2 * t + p;
                const int gn = nc * 64 + j * 8 + c2;
                const float b0v = fc1_b[gn], b1v = fc1_b[gn + 1];
                float v0 = gelu_fast(c1[j][0] + b0v);
                float v1 = gelu_fast(c1[j][1] + b1v);
                float v2 = gelu_fast(c1[j][2] + b0v);
                float v3 = gelu_fast(c1[j][3] + b1v);
                pa[t][2*p]     = packbf(v0, v1);
                pa[t][2*p + 1] = packbf(v2, v3);
            }
        }

#pragma unroll
        for (int u2 = 0; u2 < 2; u2++)
#pragma unroll
            for (int j2 = 0; j2 < 16; j2++) {
                const uint4 B = WB2[(u2 * 16 + j2) * 32 + lane];
                mma16816(hacc[j2], pa[2*u2],     B.x, B.y);
                mma16816(hacc[j2], pa[2*u2 + 1], B.z, B.w);
            }
    }

    {
        float* base0 = io + (tok0 + warp * 16 + r) * EDIM;
        float* base1 = base0 + 8 * EDIM;
#pragma unroll
        for (int j2 = 0; j2 < 16; j2++) {
            const int col = j2 * 8 + c2;
            const float b0v = fc2_b[col], b1v = fc2_b[col + 1];
            float2 t0 = *(float2*)(base0 + col);
            t0.x += hacc[j2][0] + b0v;
            t0.y += hacc[j2][1] + b1v;
            *(float2*)(base0 + col) = t0;
            float2 t1 = *(float2*)(base1 + col);
            t1.x += hacc[j2][2] + b0v;
            t1.y += hacc[j2][3] + b1v;
            *(float2*)(base1 + col) = t1;
        }
    }
}

extern "C" void kernel_launch(void* const* d_in, const int* in_sizes, int n_in,
                              void* d_out, int out_size)
{
    const float* x      = (const float*)d_in[0];
    const float* qkv_w  = (const float*)d_in[1];
    const float* qkv_b  = (const float*)d_in[2];
    const float* proj_w = (const float*)d_in[3];
    const float* proj_b = (const float*)d_in[4];
    const float* ln1_s  = (const float*)d_in[5];
    const float* ln1_b  = (const float*)d_in[6];
    const float* ln2_s  = (const float*)d_in[7];
    const float* ln2_b  = (const float*)d_in[8];
    const float* fc1_w  = (const float*)d_in[9];
    const float* fc1_b  = (const float*)d_in[10];
    const float* fc2_w  = (const float*)d_in[11];
    const float* fc2_b  = (const float*)d_in[12];
    float* out = (float*)d_out;

    cudaFuncSetAttribute(attn_kernel, cudaFuncAttributeMaxDynamicSharedMemorySize, SM1_BYTES);
    cudaFuncSetAttribute(mlp_kernel,  cudaFuncAttributeMaxDynamicSharedMemorySize, SM2_BYTES);

    pack_qkvp<<<96, 256>>>(qkv_w);
    pack_projp<<<32, 256>>>(proj_w);
    conv_fc1p<<<128, 256>>>(fc1_w);
    conv_fc2p<<<128, 256>>>(fc2_w);
    attn_kernel<<<2048, 256, SM1_BYTES>>>(x, qkv_b, proj_b, ln1_s, ln1_b, out);
    mlp_kernel<<<2048, 256, SM2_BYTES>>>(out, ln2_s, ln2_b, fc1_b, fc2_b);
}